// round 9
// baseline (speedup 1.0000x reference)
#include <cuda_runtime.h>
#include <math.h>

#define H 1024
#define V 50257
#define S 4096
#define G3H 3072

#define LRPB 8                                   // logits rows per tile (8 warps)
#define N_TILES ((V + LRPB - 1) / LRPB)          // 6283
#define NBLK 592                                 // 148 SM x 4, one wave
#define TILES_PER_BLK ((N_TILES + NBLK - 1) / NBLK)   // 11
#define N_SC_BLOCKS 512                          // scores+context fused grid
#define N_GATE_BLOCKS 768

// ---- scratch (__device__ globals; allocation-free rule) ----
__device__ float g_gi[G3H];
__device__ float g_gh[G3H];
__device__ float g_hnew[H];
__device__ float g_ctx[H];
__device__ float g_scores[S];
__device__ float g_pmax[N_SC_BLOCKS];
__device__ float g_psum[N_SC_BLOCKS];
__device__ float g_M, g_invS;
__device__ float g_lmax[NBLK];
__device__ float g_lsum[NBLK];
__device__ float g_lse;
__device__ int   g_gcount;
__device__ int   g_scount;
__device__ int   g_sdone;
__device__ volatile int g_sready;
__device__ int   g_lcount;
__device__ int   g_dcount;
__device__ volatile int g_ready;

__device__ __forceinline__ float warp_sum(float v) {
#pragma unroll
    for (int o = 16; o; o >>= 1) v += __shfl_down_sync(0xffffffffu, v, o);
    return v;
}
__device__ __forceinline__ float warp_max(float v) {
#pragma unroll
    for (int o = 16; o; o >>= 1) v = fmaxf(v, __shfl_down_sync(0xffffffffu, v, o));
    return v;
}
__device__ __forceinline__ float sigmoidf_(float x) { return 1.0f / (1.0f + expf(-x)); }

// ============================================================================
// 1) gates (warp per row) + last-block GRU combine   [R8 shape, validated]
// ============================================================================
__global__ void gates_gru_kernel(const int* __restrict__ word,
                                 const float* __restrict__ last_context,
                                 const float* __restrict__ last_hidden,
                                 const float* __restrict__ emb_tab,
                                 const float* __restrict__ w_ih,
                                 const float* __restrict__ w_hh,
                                 const float* __restrict__ b_ih,
                                 const float* __restrict__ b_hh,
                                 float* __restrict__ out) {
    __shared__ int is_last;
    int warp = (blockIdx.x * blockDim.x + threadIdx.x) >> 5;
    int lane = threadIdx.x & 31;

    if (warp < G3H) {
        const float4* wr   = (const float4*)(w_ih + (size_t)warp * (2 * H));
        const float4* embr = (const float4*)(emb_tab + (size_t)word[0] * H);
        const float4* lc4  = (const float4*)last_context;
        float acc = 0.f;
#pragma unroll
        for (int k = 0; k < 16; k++) {
            int j = lane + k * 32;
            float4 w4 = __ldcs(wr + j);
            float4 x4 = (j < 256) ? embr[j] : lc4[j - 256];
            acc += w4.x * x4.x + w4.y * x4.y + w4.z * x4.z + w4.w * x4.w;
        }
        acc = warp_sum(acc);
        if (lane == 0) g_gi[warp] = acc + b_ih[warp];
    } else {
        int r = warp - G3H;
        const float4* wr = (const float4*)(w_hh + (size_t)r * H);
        const float4* h4 = (const float4*)last_hidden;
        float acc = 0.f;
#pragma unroll
        for (int k = 0; k < 8; k++) {
            int j = lane + k * 32;
            float4 w4 = __ldcs(wr + j);
            float4 x4 = h4[j];
            acc += w4.x * x4.x + w4.y * x4.y + w4.z * x4.z + w4.w * x4.w;
        }
        acc = warp_sum(acc);
        if (lane == 0) g_gh[r] = acc + b_hh[r];
    }

    __syncthreads();
    if (threadIdx.x == 0) {
        __threadfence();
        is_last = (atomicAdd(&g_gcount, 1) == N_GATE_BLOCKS - 1);
    }
    __syncthreads();
    if (is_last) {
        __threadfence();
#pragma unroll
        for (int k = 0; k < 4; k++) {
            int d = threadIdx.x + k * 256;
            float r = sigmoidf_(g_gi[d]       + g_gh[d]);
            float z = sigmoidf_(g_gi[d + H]   + g_gh[d + H]);
            float n = tanhf    (g_gi[d + 2*H] + r * g_gh[d + 2*H]);
            float h = last_hidden[d];
            float hn = (1.0f - z) * n + z * h;
            g_hnew[d] = hn;
            g_ctx[d]  = 0.0f;
            out[V + H + d] = hn;   // h_new output slot
        }
        if (threadIdx.x == 0) g_gcount = 0;
    }
}

// ============================================================================
// 2) FUSED scores + softmax-combine + context  (512 blocks, single wave,
//    spin-safe under __launch_bounds__(256,4))
//    Phase A: block b computes scores rows [8b, 8b+8) + softmax partials;
//             last block combines -> g_M, g_invS, sets g_sready.
//    Phase B: block b computes context chunk (d-chunk = b&3, s-chunk = b>>2).
// ============================================================================
__global__ void __launch_bounds__(256, 4)
scores_ctx_kernel(const float* __restrict__ enc,
                  float* __restrict__ attn_out) {
    __shared__ float sc[8];
    __shared__ float a_sh[32];
    __shared__ int is_last;
    int tid  = threadIdx.x;
    int wid  = tid >> 5;
    int lane = tid & 31;
    int bid  = blockIdx.x;

    // ---- Phase A: scores ----
    {
        int row = bid * 8 + wid;
        const float4* e4 = (const float4*)(enc + (size_t)row * H);
        const float4* h4 = (const float4*)g_hnew;
        float acc = 0.f;
#pragma unroll
        for (int k = 0; k < 8; k++) {
            int j = lane + k * 32;
            float4 a = e4[j], b = h4[j];
            acc += a.x * b.x + a.y * b.y + a.z * b.z + a.w * b.w;
        }
        acc = warp_sum(acc);
        if (lane == 0) { g_scores[row] = acc; sc[wid] = acc; }
    }
    __syncthreads();
    if (tid == 0) {
        float m = sc[0];
#pragma unroll
        for (int i = 1; i < 8; i++) m = fmaxf(m, sc[i]);
        float s = 0.f;
#pragma unroll
        for (int i = 0; i < 8; i++) s += expf(sc[i] - m);
        g_pmax[bid] = m;
        g_psum[bid] = s;
        __threadfence();
        is_last = (atomicAdd(&g_scount, 1) == N_SC_BLOCKS - 1);
    }
    __syncthreads();
    if (is_last) {
        __threadfence();
        __shared__ float red[8];
        float m = fmaxf(g_pmax[tid], g_pmax[tid + 256]);
        float mm = warp_max(m);
        if (lane == 0) red[wid] = mm;
        __syncthreads();
        float M = red[0];
#pragma unroll
        for (int i = 1; i < 8; i++) M = fmaxf(M, red[i]);
        float s = g_psum[tid] * expf(g_pmax[tid] - M)
                + g_psum[tid + 256] * expf(g_pmax[tid + 256] - M);
        s = warp_sum(s);
        __syncthreads();
        if (lane == 0) red[wid] = s;
        __syncthreads();
        if (tid == 0) {
            float t = 0.f;
#pragma unroll
            for (int i = 0; i < 8; i++) t += red[i];
            g_M = M; g_invS = 1.0f / t;
            g_scount = 0;
            __threadfence();
            g_sready = 1;
        }
    }

    // ---- spin until softmax stats ready (all 512 blocks co-resident) ----
    if (tid == 0) {
        while (g_sready == 0) { }
    }
    __syncthreads();
    __threadfence();
    float M    = *(volatile float*)&g_M;
    float invS = *(volatile float*)&g_invS;

    // ---- Phase B: context chunk ----
    {
        int dci = bid & 3;          // 4 d-chunks of 256
        int sci = bid >> 2;         // 128 s-chunks of 32
        int s0  = sci * 32;
        int d   = dci * 256 + tid;

        if (tid < 32) {
            float a = expf(g_scores[s0 + tid] - M) * invS;
            a_sh[tid] = a;
            if (dci == 0) attn_out[s0 + tid] = a;
        }
        __syncthreads();

        const float* ep = enc + (size_t)s0 * H + d;
        float a0 = 0.f, a1 = 0.f, a2 = 0.f, a3 = 0.f;
#pragma unroll
        for (int i = 0; i < 32; i += 4) {
            a0 += a_sh[i]     * ep[(size_t)(i)     * H];
            a1 += a_sh[i + 1] * ep[(size_t)(i + 1) * H];
            a2 += a_sh[i + 2] * ep[(size_t)(i + 2) * H];
            a3 += a_sh[i + 3] * ep[(size_t)(i + 3) * H];
        }
        atomicAdd(&g_ctx[d], (a0 + a1) + (a2 + a3));
    }

    // reset spin flag for next replay
    __syncthreads();
    if (tid == 0) {
        __threadfence();
        if (atomicAdd(&g_sdone, 1) == N_SC_BLOCKS - 1) {
            g_sdone = 0;
            g_sready = 0;
        }
    }
}

// ============================================================================
// 3) PERSISTENT logits: sync-free mainloop (per-warp running lse),
//    in-kernel lse combine + spin + subtract + single final store.
// ============================================================================
__global__ void __launch_bounds__(256, 4)
logits_kernel(const float* __restrict__ out_w,
              const float* __restrict__ out_b,
              float* __restrict__ out) {
    __shared__ float4 x4[512];                      // [h_new ; ctx]
    __shared__ float stash[TILES_PER_BLK * LRPB];   // 88 logits
    __shared__ float sm_m[LRPB], sm_s[LRPB];
    __shared__ float red[8];
    __shared__ int is_last;
    float* xs = (float*)x4;
    int tid  = threadIdx.x;
    int wid  = tid >> 5;
    int lane = tid & 31;
    int bid  = blockIdx.x;

    for (int i = tid; i < H; i += 256) {
        xs[i]     = g_hnew[i];
        xs[H + i] = g_ctx[i];
    }
    __syncthreads();

    int t0 = bid * TILES_PER_BLK;
    int t1 = min(t0 + TILES_PER_BLK, N_TILES);

    // sync-free: each warp streams its own rows, keeps private running (m,s)
    float m_run = -1e30f, s_run = 0.f;
    for (int t = t0; t < t1; t++) {
        int row = t * LRPB + wid;
        float acc = 0.f;
        if (row < V) {
            const float4* wr = (const float4*)(out_w + (size_t)row * (2 * H));
#pragma unroll
            for (int k = 0; k < 16; k++) {
                int j = lane + k * 32;
                float4 w4 = __ldcs(wr + j);
                float4 v4 = x4[j];
                acc += w4.x * v4.x + w4.y * v4.y + w4.z * v4.z + w4.w * v4.w;
            }
        }
        acc = warp_sum(acc);
        if (lane == 0 && row < V) {
            float logit = acc + out_b[row];
            stash[(t - t0) * LRPB + wid] = logit;
            float M2 = fmaxf(m_run, logit);
            s_run = s_run * expf(m_run - M2) + expf(logit - M2);
            m_run = M2;
        }
    }
    if (lane == 0) { sm_m[wid] = m_run; sm_s[wid] = s_run; }
    __syncthreads();

    // publish per-block lse partial; last block combines
    if (tid == 0) {
        float m = sm_m[0];
#pragma unroll
        for (int i = 1; i < LRPB; i++) m = fmaxf(m, sm_m[i]);
        float s = 0.f;
#pragma unroll
        for (int i = 0; i < LRPB; i++) s += sm_s[i] * expf(sm_m[i] - m);
        g_lmax[bid] = m;
        g_lsum[bid] = s;
        __threadfence();
        is_last = (atomicAdd(&g_lcount, 1) == NBLK - 1);
    }
    __syncthreads();

    if (is_last) {
        __threadfence();
        float m = -1e30f;
        for (int i = tid; i < NBLK; i += 256) m = fmaxf(m, g_lmax[i]);
        float mm = warp_max(m);
        if (lane == 0) red[wid] = mm;
        __syncthreads();
        float M = red[0];
#pragma unroll
        for (int i = 1; i < 8; i++) M = fmaxf(M, red[i]);
        float s = 0.f;
        for (int i = tid; i < NBLK; i += 256) s += g_lsum[i] * expf(g_lmax[i] - M);
        s = warp_sum(s);
        __syncthreads();
        if (lane == 0) red[wid] = s;
        __syncthreads();
        if (tid == 0) {
            float t = 0.f;
#pragma unroll
            for (int i = 0; i < 8; i++) t += red[i];
            g_lse = M + logf(t);
            g_lcount = 0;
            __threadfence();
            g_ready = 1;
        }
        // context output slot (piggyback)
        for (int i = tid; i < H; i += 256) out[V + i] = xs[H + i];
    }

    // spin until lse ready (single wave by __launch_bounds__(256,4))
    if (tid == 0) {
        while (g_ready == 0) { }
    }
    __syncthreads();
    __threadfence();
    float lse = *(volatile float*)&g_lse;

    // subtract from stash, single store of final log-probs
    int nrows = (t1 - t0) * LRPB;
    for (int i = tid; i < nrows; i += 256) {
        int row = t0 * LRPB + i;
        if (row < V) out[row] = stash[i] - lse;
    }

    // done-counter: last finisher resets flags for the next graph replay
    __syncthreads();
    if (tid == 0) {
        __threadfence();
        if (atomicAdd(&g_dcount, 1) == NBLK - 1) {
            g_dcount = 0;
            g_ready  = 0;
        }
    }
}

// ============================================================================
extern "C" void kernel_launch(void* const* d_in, const int* in_sizes, int n_in,
                              void* d_out, int out_size) {
    const int*   word  = (const int*)  d_in[0];
    const float* lc    = (const float*)d_in[1];
    const float* lh    = (const float*)d_in[2];
    const float* enc   = (const float*)d_in[3];
    const float* emb   = (const float*)d_in[4];
    const float* w_ih  = (const float*)d_in[5];
    const float* w_hh  = (const float*)d_in[6];
    const float* b_ih  = (const float*)d_in[7];
    const float* b_hh  = (const float*)d_in[8];
    const float* out_w = (const float*)d_in[9];
    const float* out_b = (const float*)d_in[10];
    float* out = (float*)d_out;

    float* attn_slot = out + V + 2 * H;

    gates_gru_kernel<<<N_GATE_BLOCKS, 256>>>(word, lc, lh, emb, w_ih, w_hh, b_ih, b_hh, out);
    scores_ctx_kernel<<<N_SC_BLOCKS, 256>>>(enc, attn_slot);
    logits_kernel<<<NBLK, 256>>>(out_w, out_b, out);
}

// round 10
// speedup vs baseline: 1.1328x; 1.1328x over previous
#include <cuda_runtime.h>
#include <math.h>

#define H 1024
#define V 50257
#define S 4096
#define G3H 3072

#define LRPB 8                                   // logits rows per tile (8 warps)
#define N_TILES ((V + LRPB - 1) / LRPB)          // 6283
#define NBLK 592                                 // 148 SM x 4, one wave
#define TILES_PER_BLK ((N_TILES + NBLK - 1) / NBLK)   // 11
#define N_SCORE_BLOCKS (S / 8)                   // 512
#define N_GATE_BLOCKS 768

// ---- scratch (__device__ globals; allocation-free rule) ----
__device__ float g_gi[G3H];
__device__ float g_gh[G3H];
__device__ float g_hnew[H];
__device__ float g_ctx[H];
__device__ float g_scores[S];
__device__ float g_pmax[N_SCORE_BLOCKS];
__device__ float g_psum[N_SCORE_BLOCKS];
__device__ float g_M, g_invS;
__device__ float g_lmax[NBLK];
__device__ float g_lsum[NBLK];
__device__ float g_lse;
__device__ int   g_gcount;
__device__ int   g_scount;
__device__ int   g_lcount;
__device__ int   g_dcount;
__device__ volatile int g_ready;

__device__ __forceinline__ float warp_sum(float v) {
#pragma unroll
    for (int o = 16; o; o >>= 1) v += __shfl_down_sync(0xffffffffu, v, o);
    return v;
}
__device__ __forceinline__ float warp_max(float v) {
#pragma unroll
    for (int o = 16; o; o >>= 1) v = fmaxf(v, __shfl_down_sync(0xffffffffu, v, o));
    return v;
}
__device__ __forceinline__ float sigmoidf_(float x) { return 1.0f / (1.0f + expf(-x)); }

// ============================================================================
// 1) gates: x staged in SHARED (logits-winning shape) + last-block GRU.
//    Blocks [0,384): gi rows, x = [emb ; last_context] (2048 floats in smem).
//    Blocks [384,768): gh rows, x = h (1024 floats in smem).
// ============================================================================
__global__ void gates_gru_kernel(const int* __restrict__ word,
                                 const float* __restrict__ last_context,
                                 const float* __restrict__ last_hidden,
                                 const float* __restrict__ emb_tab,
                                 const float* __restrict__ w_ih,
                                 const float* __restrict__ w_hh,
                                 const float* __restrict__ b_ih,
                                 const float* __restrict__ b_hh,
                                 float* __restrict__ out) {
    __shared__ float4 x4[512];           // gi: 2048 floats; gh: first 1024 used
    __shared__ int is_last;
    float* xs = (float*)x4;
    int tid  = threadIdx.x;
    int wid  = tid >> 5;
    int lane = tid & 31;
    bool gi_block = (blockIdx.x < N_GATE_BLOCKS / 2);

    if (gi_block) {
        const float* embr = emb_tab + (size_t)word[0] * H;
        for (int i = tid; i < H; i += 256) {
            xs[i]     = embr[i];
            xs[H + i] = last_context[i];
        }
    } else {
        for (int i = tid; i < H; i += 256) xs[i] = last_hidden[i];
    }
    __syncthreads();

    if (gi_block) {
        int row = blockIdx.x * 8 + wid;                       // 0..3071
        const float4* wr = (const float4*)(w_ih + (size_t)row * (2 * H));
        float acc = 0.f;
#pragma unroll
        for (int k = 0; k < 16; k++) {
            int j = lane + k * 32;
            float4 w4 = __ldcs(wr + j);
            float4 v4 = x4[j];
            acc += w4.x * v4.x + w4.y * v4.y + w4.z * v4.z + w4.w * v4.w;
        }
        acc = warp_sum(acc);
        if (lane == 0) g_gi[row] = acc + b_ih[row];
    } else {
        int row = (blockIdx.x - N_GATE_BLOCKS / 2) * 8 + wid; // 0..3071
        const float4* wr = (const float4*)(w_hh + (size_t)row * H);
        float acc = 0.f;
#pragma unroll
        for (int k = 0; k < 8; k++) {
            int j = lane + k * 32;
            float4 w4 = __ldcs(wr + j);
            float4 v4 = x4[j];
            acc += w4.x * v4.x + w4.y * v4.y + w4.z * v4.z + w4.w * v4.w;
        }
        acc = warp_sum(acc);
        if (lane == 0) g_gh[row] = acc + b_hh[row];
    }

    __syncthreads();
    if (tid == 0) {
        __threadfence();
        is_last = (atomicAdd(&g_gcount, 1) == N_GATE_BLOCKS - 1);
    }
    __syncthreads();
    if (is_last) {
        __threadfence();
#pragma unroll
        for (int k = 0; k < 4; k++) {
            int d = tid + k * 256;
            float r = sigmoidf_(g_gi[d]       + g_gh[d]);
            float z = sigmoidf_(g_gi[d + H]   + g_gh[d + H]);
            float n = tanhf    (g_gi[d + 2*H] + r * g_gh[d + 2*H]);
            float h = last_hidden[d];
            float hn = (1.0f - z) * n + z * h;
            g_hnew[d] = hn;
            g_ctx[d]  = 0.0f;
            out[V + H + d] = hn;   // h_new output slot
        }
        if (tid == 0) g_gcount = 0;
    }
}

// ============================================================================
// 2) scores (warp per row) + last-block softmax combine   [R8, validated]
// ============================================================================
__global__ void scores_kernel(const float* __restrict__ enc) {
    __shared__ float sc[8];
    __shared__ int is_last;
    int wid  = threadIdx.x >> 5;
    int lane = threadIdx.x & 31;
    int row  = blockIdx.x * 8 + wid;

    const float4* e4 = (const float4*)(enc + (size_t)row * H);
    const float4* h4 = (const float4*)g_hnew;
    float acc = 0.f;
#pragma unroll
    for (int k = 0; k < 8; k++) {
        int j = lane + k * 32;
        float4 a = e4[j], b = h4[j];
        acc += a.x * b.x + a.y * b.y + a.z * b.z + a.w * b.w;
    }
    acc = warp_sum(acc);
    if (lane == 0) { g_scores[row] = acc; sc[wid] = acc; }
    __syncthreads();
    if (threadIdx.x == 0) {
        float m = sc[0];
#pragma unroll
        for (int i = 1; i < 8; i++) m = fmaxf(m, sc[i]);
        float s = 0.f;
#pragma unroll
        for (int i = 0; i < 8; i++) s += expf(sc[i] - m);
        g_pmax[blockIdx.x] = m;
        g_psum[blockIdx.x] = s;
        __threadfence();
        is_last = (atomicAdd(&g_scount, 1) == N_SCORE_BLOCKS - 1);
    }
    __syncthreads();
    if (is_last) {
        __threadfence();
        __shared__ float red[8];
        int tid = threadIdx.x;
        int lane2 = tid & 31;
        float m = fmaxf(g_pmax[tid], g_pmax[tid + 256]);
        float mm = warp_max(m);
        if (lane2 == 0) red[tid >> 5] = mm;
        __syncthreads();
        float M = red[0];
#pragma unroll
        for (int i = 1; i < 8; i++) M = fmaxf(M, red[i]);
        float s = g_psum[tid] * expf(g_pmax[tid] - M)
                + g_psum[tid + 256] * expf(g_pmax[tid + 256] - M);
        s = warp_sum(s);
        __syncthreads();
        if (lane2 == 0) red[tid >> 5] = s;
        __syncthreads();
        if (tid == 0) {
            float t = 0.f;
#pragma unroll
            for (int i = 0; i < 8; i++) t += red[i];
            g_M = M; g_invS = 1.0f / t;
            g_scount = 0;
        }
    }
}

// ============================================================================
// 3) context: grid (4, 256) x 256 thr; 16 unrolled rows per thread  [R8]
// ============================================================================
__global__ void context_kernel(const float* __restrict__ enc,
                               float* __restrict__ attn_out) {
    __shared__ float a_sh[16];
    int tid = threadIdx.x;
    int s0  = blockIdx.y * 16;
    int d   = blockIdx.x * 256 + tid;

    if (tid < 16) {
        float a = expf(g_scores[s0 + tid] - g_M) * g_invS;
        a_sh[tid] = a;
        if (blockIdx.x == 0) attn_out[s0 + tid] = a;
    }
    __syncthreads();

    const float* ep = enc + (size_t)s0 * H + d;
    float acc = 0.f;
#pragma unroll
    for (int i = 0; i < 16; i++)
        acc += a_sh[i] * ep[(size_t)i * H];
    atomicAdd(&g_ctx[d], acc);
}

// ============================================================================
// 4) PERSISTENT logits  [R8, validated: 78.6us @ 67% DRAM]
// ============================================================================
__global__ void __launch_bounds__(256, 4)
logits_kernel(const float* __restrict__ out_w,
              const float* __restrict__ out_b,
              float* __restrict__ out) {
    __shared__ float4 x4[512];                      // [h_new ; ctx]
    __shared__ float stash[TILES_PER_BLK * LRPB];   // 88 logits
    __shared__ float lg[LRPB];
    __shared__ float red[8];
    __shared__ int is_last;
    float* xs = (float*)x4;
    int tid  = threadIdx.x;
    int wid  = tid >> 5;
    int lane = tid & 31;
    int bid  = blockIdx.x;

    for (int i = tid; i < H; i += 256) {
        xs[i]     = g_hnew[i];
        xs[H + i] = g_ctx[i];
    }
    __syncthreads();

    int t0 = bid * TILES_PER_BLK;
    int t1 = min(t0 + TILES_PER_BLK, N_TILES);

    float m_run = -1e30f, s_run = 0.f;
    for (int t = t0; t < t1; t++) {
        int row = t * LRPB + wid;
        float logit = -1e30f;
        if (row < V) {
            const float4* wr = (const float4*)(out_w + (size_t)row * (2 * H));
            float acc = 0.f;
#pragma unroll
            for (int k = 0; k < 16; k++) {
                int j = lane + k * 32;
                float4 w4 = __ldcs(wr + j);
                float4 v4 = x4[j];
                acc += w4.x * v4.x + w4.y * v4.y + w4.z * v4.z + w4.w * v4.w;
            }
            acc = warp_sum(acc);
            if (lane == 0) logit = acc + out_b[row];
        }
        if (lane == 0) {
            lg[wid] = logit;
            stash[(t - t0) * LRPB + wid] = logit;
        }
        __syncthreads();
        if (tid == 0) {
            float m = lg[0];
#pragma unroll
            for (int i = 1; i < LRPB; i++) m = fmaxf(m, lg[i]);
            float M2 = fmaxf(m_run, m);
            float ss = s_run * expf(m_run - M2);
#pragma unroll
            for (int i = 0; i < LRPB; i++) ss += expf(lg[i] - M2);
            m_run = M2; s_run = ss;
        }
        __syncthreads();
    }

    if (tid == 0) {
        g_lmax[bid] = m_run;
        g_lsum[bid] = s_run;
        __threadfence();
        is_last = (atomicAdd(&g_lcount, 1) == NBLK - 1);
    }
    __syncthreads();

    if (is_last) {
        __threadfence();
        float m = -1e30f;
        for (int i = tid; i < NBLK; i += 256) m = fmaxf(m, g_lmax[i]);
        float mm = warp_max(m);
        if (lane == 0) red[wid] = mm;
        __syncthreads();
        float M = red[0];
#pragma unroll
        for (int i = 1; i < 8; i++) M = fmaxf(M, red[i]);
        float s = 0.f;
        for (int i = tid; i < NBLK; i += 256) s += g_lsum[i] * expf(g_lmax[i] - M);
        s = warp_sum(s);
        __syncthreads();
        if (lane == 0) red[wid] = s;
        __syncthreads();
        if (tid == 0) {
            float t = 0.f;
#pragma unroll
            for (int i = 0; i < 8; i++) t += red[i];
            g_lse = M + logf(t);
            g_lcount = 0;
            __threadfence();
            g_ready = 1;
        }
        for (int i = tid; i < H; i += 256) out[V + i] = xs[H + i];  // context slot
    }

    if (tid == 0) {
        while (g_ready == 0) { }
    }
    __syncthreads();
    __threadfence();
    float lse = *(volatile float*)&g_lse;

    int nrows = (t1 - t0) * LRPB;
    for (int i = tid; i < nrows; i += 256) {
        int row = t0 * LRPB + i;
        if (row < V) out[row] = stash[i] - lse;
    }

    __syncthreads();
    if (tid == 0) {
        __threadfence();
        if (atomicAdd(&g_dcount, 1) == NBLK - 1) {
            g_dcount = 0;
            g_ready  = 0;
        }
    }
}

// ============================================================================
extern "C" void kernel_launch(void* const* d_in, const int* in_sizes, int n_in,
                              void* d_out, int out_size) {
    const int*   word  = (const int*)  d_in[0];
    const float* lc    = (const float*)d_in[1];
    const float* lh    = (const float*)d_in[2];
    const float* enc   = (const float*)d_in[3];
    const float* emb   = (const float*)d_in[4];
    const float* w_ih  = (const float*)d_in[5];
    const float* w_hh  = (const float*)d_in[6];
    const float* b_ih  = (const float*)d_in[7];
    const float* b_hh  = (const float*)d_in[8];
    const float* out_w = (const float*)d_in[9];
    const float* out_b = (const float*)d_in[10];
    float* out = (float*)d_out;

    float* attn_slot = out + V + 2 * H;

    gates_gru_kernel<<<N_GATE_BLOCKS, 256>>>(word, lc, lh, emb, w_ih, w_hh, b_ih, b_hh, out);
    scores_kernel<<<N_SCORE_BLOCKS, 256>>>(enc);
    {
        dim3 g(4, 256);
        context_kernel<<<g, 256>>>(enc, attn_slot);
    }
    logits_kernel<<<NBLK, 256>>>(out_w, out_b, out);
}